// round 10
// baseline (speedup 1.0000x reference)
#include <cuda_runtime.h>
#include <math.h>

#define BB 64
#define SS 512
#define HH 768
#define NT 36
#define TSTART 34
#define TSTOP 35
#define KQ 192             // K per quarter (768/4)
#define SCAN_BLOCKS 128
#define GEMM_BLOCKS 512    // 64 rows per block
#define CHUNK 64           // rows per readiness chunk (8 per batch)

// Scratch (device globals — no allocation allowed)
__device__ float g_emit [BB * SS * NT];
__device__ float g_eemit[BB * SS * NT];
__device__ float g_lossb[BB];
__device__ int   g_done [BB * 8];         // per-(batch,64-chunk) readiness
__device__ int   g_nllcnt;

// ---------------- f32x2 helpers ----------------
__device__ __forceinline__ unsigned long long pack2(float a, float b) {
    unsigned long long r;
    asm("mov.b64 %0, {%1, %2};" : "=l"(r) : "f"(a), "f"(b));
    return r;
}
__device__ __forceinline__ void unpack2(unsigned long long v, float& a, float& b) {
    asm("mov.b64 {%0, %1}, %2;" : "=f"(a), "=f"(b) : "l"(v));
}
__device__ __forceinline__ unsigned long long fma2(unsigned long long a,
                                                   unsigned long long b,
                                                   unsigned long long c) {
    unsigned long long d;
    asm("fma.rn.f32x2 %0, %1, %2, %3;" : "=l"(d) : "l"(a), "l"(b), "l"(c));
    return d;
}
__device__ __forceinline__ unsigned long long add2(unsigned long long a,
                                                   unsigned long long b) {
    unsigned long long d;
    asm("add.rn.f32x2 %0, %1, %2;" : "=l"(d) : "l"(a), "l"(b));
    return d;
}
__device__ __forceinline__ void barr64() {
    asm volatile("bar.sync 0, 64;" ::: "memory");
}
__device__ __forceinline__ void wait_flag(int idx) {
    volatile int* f = &g_done[idx];
    while (*f == 0) __nanosleep(64);
}

// ---------------- init ----------------
__global__ void init_kernel() {
    int i = threadIdx.x + blockIdx.x * blockDim.x;
    if (i < BB * 8) g_done[i] = 0;
    if (i == 0) g_nllcnt = 0;
}

union SmemU {
    float Xs[4][16][64];           // 16384 B  k-major X tiles (per quarter)
    float part[3][64][36];         // 27648 B  quarter partials
    char  uu[(SS - 1) * NT];       // 18396 B  Tsh / backpointers
};

// GEMM inner for one column-half. NP = f32x2 pairs (8 for cols[0,16), 10 for [16,36)).
template<int NP>
__device__ __forceinline__ void gemm_half(
    SmemU* u, const float* __restrict__ x1, const float* __restrict__ W,
    const float* __restrict__ bias, const int* src,
    int q, int h, int lane, int rowbase)
{
    const int coloff = h * 16;
    unsigned long long acc[2][NP];
#pragma unroll
    for (int r2 = 0; r2 < 2; r2++)
#pragma unroll
        for (int p = 0; p < NP; p++) acc[r2][p] = 0ull;

    const int kbase = q * KQ;
    const int tid64 = h * 32 + lane;

    for (int kt = 0; kt < KQ / 16; kt++) {
        const int k0 = kbase + kt * 16;
        // stage 64 rows x 16 k for this quarter (both half-warps cooperate)
#pragma unroll
        for (int it = 0; it < 4; it++) {
            int idx = tid64 + it * 64;
            int rr = idx & 63, c4 = idx >> 6;
            float4 v = __ldcg(reinterpret_cast<const float4*>(x1 + src[rr] + k0) + c4);
            u->Xs[q][c4 * 4 + 0][rr] = v.x;
            u->Xs[q][c4 * 4 + 1][rr] = v.y;
            u->Xs[q][c4 * 4 + 2][rr] = v.z;
            u->Xs[q][c4 * 4 + 3][rr] = v.w;
        }
        __syncthreads();

#pragma unroll
        for (int kk = 0; kk < 16; kk++) {
            float xa = u->Xs[q][kk][lane];
            float xb = u->Xs[q][kk][lane + 32];
            unsigned long long pa = pack2(xa, xa);
            unsigned long long pb = pack2(xb, xb);
            const ulonglong2* wrow =
                reinterpret_cast<const ulonglong2*>(W + (k0 + kk) * 36 + coloff);
#pragma unroll
            for (int p = 0; p < NP / 2; p++) {
                ulonglong2 w = __ldg(wrow + p);     // uniform LDG.128, L1-hit
                acc[0][2 * p]     = fma2(pa, w.x, acc[0][2 * p]);
                acc[0][2 * p + 1] = fma2(pa, w.y, acc[0][2 * p + 1]);
                acc[1][2 * p]     = fma2(pb, w.x, acc[1][2 * p]);
                acc[1][2 * p + 1] = fma2(pb, w.y, acc[1][2 * p + 1]);
            }
        }
        __syncthreads();
    }

    // write partials (quarters 1..3) / finalize (quarter 0)
    if (q != 0) {
#pragma unroll
        for (int r2 = 0; r2 < 2; r2++) {
            const int row = lane + 32 * r2;
#pragma unroll
            for (int p = 0; p < NP; p++) {
                float a, b; unpack2(acc[r2][p], a, b);
                u->part[q - 1][row][coloff + 2 * p]     = a;
                u->part[q - 1][row][coloff + 2 * p + 1] = b;
            }
        }
    }
    __syncthreads();
    if (q == 0) {
#pragma unroll
        for (int r2 = 0; r2 < 2; r2++) {
            const int row = lane + 32 * r2;
            const long long grow = rowbase + row;
            float ev[2 * NP], eev[2 * NP];
#pragma unroll
            for (int p = 0; p < NP; p++) {
                float a, b; unpack2(acc[r2][p], a, b);
                int c0 = coloff + 2 * p;
                float v0 = a + u->part[0][row][c0] + u->part[1][row][c0] +
                           u->part[2][row][c0] + bias[c0];
                float v1 = b + u->part[0][row][c0 + 1] + u->part[1][row][c0 + 1] +
                           u->part[2][row][c0 + 1] + bias[c0 + 1];
                v0 = (v0 >= 0.f) ? v0 : 0.01f * v0;
                v1 = (v1 >= 0.f) ? v1 : 0.01f * v1;
                ev[2 * p] = v0;  ev[2 * p + 1] = v1;
                eev[2 * p] = __expf(v0);  eev[2 * p + 1] = __expf(v1);
            }
            float4* pe  = reinterpret_cast<float4*>(g_emit  + grow * 36 + coloff);
            float4* pee = reinterpret_cast<float4*>(g_eemit + grow * 36 + coloff);
#pragma unroll
            for (int c4 = 0; c4 < NP / 2; c4++) {
                pe[c4]  = make_float4(ev[4*c4],  ev[4*c4+1],  ev[4*c4+2],  ev[4*c4+3]);
                pee[c4] = make_float4(eev[4*c4], eev[4*c4+1], eev[4*c4+2], eev[4*c4+3]);
            }
        }
    }
}

// ---------------- fused kernel ----------------
// blocks [0,64):    NLL scan (batch bid)
// blocks [64,128):  Viterbi (batch bid-64)
// blocks [128,640): GEMM, chunk-major: c=(bid-128)>>6, b=(bid-128)&63, 64 rows
// block  640:       loss reducer
__global__ __launch_bounds__(256, 3) void fused_kernel(
    const float* __restrict__ x1, const int* __restrict__ hidx,
    const float* __restrict__ W, const float* __restrict__ bias,
    const int* __restrict__ tags, const float* __restrict__ trans,
    float* __restrict__ out)
{
    __shared__ __align__(16) SmemU u;
    __shared__ int   src[64];
    __shared__ __align__(16) float buf[2][NT];
    __shared__ float red[64];
    __shared__ int   ired[64];
    __shared__ int   sh_xlen, sh_last;

    const int tid = threadIdx.x;
    const int bid = blockIdx.x;

    if (bid >= SCAN_BLOCKS && bid < SCAN_BLOCKS + GEMM_BLOCKS) {
        // ================= GEMM =================
        const int gb = bid - SCAN_BLOCKS;
        const int c  = gb >> 6;          // chunk 0..7
        const int b  = gb & 63;          // batch
        const int rowbase = b * SS + c * CHUNK;
        const int warp = tid >> 5;
        const int q = warp >> 1;         // k-quarter
        const int h = warp & 1;          // col half
        const int lane = tid & 31;

        if (tid < 64) {
            int g = rowbase + tid;
            src[tid] = (b << 9) * HH + hidx[g] * HH;
        }
        __syncthreads();

        if (h == 0) gemm_half<8 >(&u, x1, W, bias, src, q, 0, lane, rowbase);
        else        gemm_half<10>(&u, x1, W, bias, src, q, 1, lane, rowbase);

        __syncthreads();
        if (tid == 0) {
            __threadfence();
            atomicExch(&g_done[b * 8 + c], 1);
        }
        return;
    }

    if (bid >= SCAN_BLOCKS + GEMM_BLOCKS) {
        // ================= loss reducer =================
        if (tid == 0) {
            volatile int* c = &g_nllcnt;
            while (*c < BB) __nanosleep(256);
            __threadfence();
            float a = 0.f;
            for (int i = 0; i < BB; i++) a += g_lossb[i];
            out[0] = a;
        }
        return;
    }

    // ================= SCANS (threads 0-63 only) =================
    if (tid >= 64) return;

    const int b = bid & 63;
    const bool viterbi = (bid >= BB);
    const int j = tid;

    // xlen = max(head_indexes[b, :])
    {
        int lm = 0;
        for (int s = tid; s < SS; s += 64) lm = max(lm, hidx[b * SS + s]);
        ired[tid] = lm;
        barr64();
        if (tid == 0) {
            int m = 0;
            for (int i = 0; i < 64; i++) m = max(m, ired[i]);
            sh_xlen = m;
        }
        barr64();
    }
    const int xlen = sh_xlen;
    const int cmax = (xlen - 1) >> 6;    // 64-row chunks
    int sready = 0;

    if (!viterbi) {
        // ---------------- NLL (scaled forward) ----------------
        float* Tsh = reinterpret_cast<float*>(u.uu);
        for (int i = tid; i < NT * NT; i += 64) Tsh[i] = trans[i];
        barr64();

        unsigned long long Ecol2[18];
        float Cl = 0.f;
        if (j < NT) {
#pragma unroll
            for (int p = 0; p < 18; p++)
                Ecol2[p] = pack2(__expf(Tsh[(2 * p) * NT + j]),
                                 __expf(Tsh[(2 * p + 1) * NT + j]));
        }

        if (tid == 0) { wait_flag(b * 8 + 0); sready = 1; __threadfence(); }
        barr64();

        if (j < NT)
            buf[0][j] = __expf(g_emit[(b * SS) * NT + j] + Tsh[TSTART * NT + j]);
        barr64();

        const float* ee = g_eemit + (long long)b * SS * NT;
        float eenext = (xlen > 1 && j < NT) ? ee[NT + j] : 0.f;
        int t = 1;
        for (int c = 0; c <= cmax; c++) {
            const int wc = min(c + 1, cmax);
            if (tid == 0) {
                for (; sready <= wc; sready++) wait_flag(b * 8 + sready);
                __threadfence();
            }
            barr64();
            const int tend = min((c + 1) * CHUNK, xlen);
            for (; t < tend; t++) {
                const int cur = t & 1, prev = cur ^ 1;
                float eecur = eenext;
                if (t + 1 < xlen && j < NT) eenext = ee[(t + 1) * NT + j];
                if (j < NT) {
                    const unsigned long long* vp =
                        reinterpret_cast<const unsigned long long*>(&buf[prev][0]);
                    unsigned long long c0 = 0, c1 = 0, c2 = 0, c3 = 0;
                    float m0 = 0.f, m1 = 0.f, m2 = 0.f, m3 = 0.f;
#pragma unroll
                    for (int p = 0; p < 16; p += 4) {
                        unsigned long long v0 = vp[p], v1 = vp[p+1], v2 = vp[p+2], v3 = vp[p+3];
                        c0 = fma2(v0, Ecol2[p],   c0);
                        c1 = fma2(v1, Ecol2[p+1], c1);
                        c2 = fma2(v2, Ecol2[p+2], c2);
                        c3 = fma2(v3, Ecol2[p+3], c3);
                        float a, bb2;
                        unpack2(v0, a, bb2); m0 = fmaxf(m0, fmaxf(a, bb2));
                        unpack2(v1, a, bb2); m1 = fmaxf(m1, fmaxf(a, bb2));
                        unpack2(v2, a, bb2); m2 = fmaxf(m2, fmaxf(a, bb2));
                        unpack2(v3, a, bb2); m3 = fmaxf(m3, fmaxf(a, bb2));
                    }
                    {
                        unsigned long long v0 = vp[16], v1 = vp[17];
                        c0 = fma2(v0, Ecol2[16], c0);
                        c1 = fma2(v1, Ecol2[17], c1);
                        float a, bb2;
                        unpack2(v0, a, bb2); m0 = fmaxf(m0, fmaxf(a, bb2));
                        unpack2(v1, a, bb2); m1 = fmaxf(m1, fmaxf(a, bb2));
                    }
                    unsigned long long cs = add2(add2(c0, c1), add2(c2, c3));
                    float sa, sbv; unpack2(cs, sa, sbv);
                    float accv = sa + sbv;
                    float m = fmaxf(fmaxf(m0, m1), fmaxf(m2, m3));
                    buf[cur][j] = accv * (1.0f / m) * eecur;
                    Cl += __logf(m);
                }
                barr64();
            }
        }
        const int lastbuf = (xlen >= 2) ? ((xlen - 1) & 1) : 0;
        if (j < NT) red[j] = buf[lastbuf][j] * __expf(Tsh[j * NT + TSTOP]);
        barr64();

        float logZ = 0.f;
        if (tid == 0) {
            float sZ = 0.f;
            for (int i = 0; i < NT; i++) sZ += red[i];
            logZ = Cl + __logf(sZ);
        }
        barr64();

        // gold score
        const int* tg = tags + b * SS;
        {
            float gp = 0.f;
            for (int s = tid; s < xlen; s += 64) {
                int cs = tg[s];
                gp += g_emit[((long long)b * SS + s) * NT + cs];
                if (s >= 1) gp += Tsh[tg[s - 1] * NT + cs];
            }
            red[tid] = gp;
        }
        barr64();
        if (tid == 0) {
            float g = 0.f;
            for (int i = 0; i < 64; i++) g += red[i];
            int li = (xlen > 0) ? (xlen - 1) : 0;
            g += Tsh[TSTART * NT + tg[0]] + Tsh[tg[li] * NT + TSTOP];
            g_lossb[b] = logZ - g;
            __threadfence();
            atomicAdd(&g_nllcnt, 1);
        }
    } else {
        // ---------------- Viterbi ----------------
        unsigned char* bp = reinterpret_cast<unsigned char*>(u.uu);
        float Tcol[NT];
        float TjS = 0.f;
        if (j < NT) {
#pragma unroll
            for (int i = 0; i < NT; i++) Tcol[i] = trans[i * NT + j];
            TjS = trans[j * NT + TSTOP];
        }

        if (tid == 0) { wait_flag(b * 8 + 0); sready = 1; __threadfence(); }
        barr64();

        if (j < NT)
            buf[0][j] = g_emit[(b * SS) * NT + j] + trans[TSTART * NT + j];
        barr64();

        const float* em = g_emit + (long long)b * SS * NT;
        float emnext = (xlen > 1 && j < NT) ? em[NT + j] : 0.f;
        int t = 1;
        for (int c = 0; c <= cmax; c++) {
            const int wc = min(c + 1, cmax);
            if (tid == 0) {
                for (; sready <= wc; sready++) wait_flag(b * 8 + sready);
                __threadfence();
            }
            barr64();
            const int tend = min((c + 1) * CHUNK, xlen);
            for (; t < tend; t++) {
                const int cur = t & 1, prev = cur ^ 1;
                float ec = emnext;
                if (t + 1 < xlen && j < NT) emnext = em[(t + 1) * NT + j];
                if (j < NT) {
                    float bb4[4] = {-1e30f, -1e30f, -1e30f, -1e30f};
                    int   bi4[4] = {0, 9, 18, 27};
#pragma unroll
                    for (int c4 = 0; c4 < 4; c4++) {
#pragma unroll
                        for (int k = 0; k < 9; k++) {
                            int i = c4 * 9 + k;
                            float v = buf[prev][i] + Tcol[i];
                            bool gt = v > bb4[c4];
                            bb4[c4] = gt ? v : bb4[c4];
                            bi4[c4] = gt ? i : bi4[c4];
                        }
                    }
                    float best = bb4[0]; int bi = bi4[0];
                    if (bb4[1] > best) { best = bb4[1]; bi = bi4[1]; }
                    if (bb4[2] > best) { best = bb4[2]; bi = bi4[2]; }
                    if (bb4[3] > best) { best = bb4[3]; bi = bi4[3]; }
                    buf[cur][j] = best + ec;
                    bp[(t - 1) * NT + j] = (unsigned char)bi;
                }
                barr64();
            }
        }
        const int lastbuf = (xlen >= 2) ? ((xlen - 1) & 1) : 0;
        if (j < NT) red[j] = buf[lastbuf][j] + TjS;
        barr64();
        if (tid == 0) {
            float bs = -1e30f; int lt = 0;
            for (int i = 0; i < NT; i++) {
                float v = red[i];
                if (v > bs) { bs = v; lt = i; }
            }
            out[1 + BB * SS + b] = bs;   // path_score
            sh_last = lt;
        }
        barr64();

        float* op = out + 1 + b * SS;
        for (int s = xlen + tid; s < SS; s += 64) op[s] = 0.f;
        if (tid == 0 && xlen > 0) {
            int tag = sh_last;
            op[xlen - 1] = (float)tag;
            for (int t2 = xlen - 1; t2 >= 1; t2--) {
                tag = bp[(t2 - 1) * NT + tag];
                op[t2 - 1] = (float)tag;
            }
        }
    }
}

extern "C" void kernel_launch(void* const* d_in, const int* in_sizes, int n_in,
                              void* d_out, int out_size) {
    const float* x1    = (const float*)d_in[0];
    const int*   hidx  = (const int*)  d_in[1];
    const int*   tags  = (const int*)  d_in[2];
    const float* W     = (const float*)d_in[3];
    const float* bias  = (const float*)d_in[4];
    const float* trans = (const float*)d_in[5];
    float* out = (float*)d_out;

    init_kernel<<<2, 256>>>();
    fused_kernel<<<SCAN_BLOCKS + GEMM_BLOCKS + 1, 256>>>(
        x1, hidx, W, bias, tags, trans, out);
}

// round 11
// speedup vs baseline: 1.0332x; 1.0332x over previous
#include <cuda_runtime.h>
#include <math.h>

#define BB 64
#define SS 512
#define HH 768
#define NT 36
#define TSTART 34
#define TSTOP 35
#define KQ 192             // K per quarter (768/4)
#define SCAN_BLOCKS 64     // one block per batch: NLL (thr 0-63) + Viterbi (thr 64-127)
#define GEMM_BLOCKS 256    // 128 rows per block
#define CHUNK 128          // rows per readiness chunk (4 per batch)

// Scratch (device globals — no allocation allowed)
__device__ float g_emit [BB * SS * NT];
__device__ float g_eemit[BB * SS * NT];
__device__ float g_lossb[BB];
__device__ int   g_done [BB * 4];         // per-(batch,128-chunk) readiness
__device__ int   g_nllcnt;

// ---------------- f32x2 helpers ----------------
__device__ __forceinline__ unsigned long long pack2(float a, float b) {
    unsigned long long r;
    asm("mov.b64 %0, {%1, %2};" : "=l"(r) : "f"(a), "f"(b));
    return r;
}
__device__ __forceinline__ void unpack2(unsigned long long v, float& a, float& b) {
    asm("mov.b64 {%0, %1}, %2;" : "=f"(a), "=f"(b) : "l"(v));
}
__device__ __forceinline__ unsigned long long fma2(unsigned long long a,
                                                   unsigned long long b,
                                                   unsigned long long c) {
    unsigned long long d;
    asm("fma.rn.f32x2 %0, %1, %2, %3;" : "=l"(d) : "l"(a), "l"(b), "l"(c));
    return d;
}
__device__ __forceinline__ unsigned long long add2(unsigned long long a,
                                                   unsigned long long b) {
    unsigned long long d;
    asm("add.rn.f32x2 %0, %1, %2;" : "=l"(d) : "l"(a), "l"(b));
    return d;
}
__device__ __forceinline__ void nbar(int id) {
    asm volatile("bar.sync %0, 64;" :: "r"(id) : "memory");
}
__device__ __forceinline__ void wait_flag(int idx) {
    volatile int* f = &g_done[idx];
    while (*f == 0) __nanosleep(64);
}

// ---------------- init ----------------
__global__ void init_kernel() {
    int i = threadIdx.x + blockIdx.x * blockDim.x;
    if (i < BB * 4) g_done[i] = 0;
    if (i == 0) g_nllcnt = 0;
}

union SmemU {
    float Xs[4][16][129];          // 33024 B  k-major X tiles, stride 129
    float part[3][128][36];        // 55296 B  quarter partials
    struct {                       // 23580 B  scan state (NLL + Viterbi coexist)
        float Tsh[NT * NT];
        unsigned char bp[(SS - 1) * NT];
    } s;
};

// GEMM inner for one column-half. NP = f32x2 pairs (8 for cols[0,16), 10 for [16,36)).
template<int NP>
__device__ __forceinline__ void gemm_half(
    SmemU* u, const float* __restrict__ x1, const float* __restrict__ W,
    const float* __restrict__ bias, const int* src,
    int q, int h, int lane, int rowbase)
{
    const int coloff = h * 16;
    unsigned long long acc[4][NP];
#pragma unroll
    for (int r4 = 0; r4 < 4; r4++)
#pragma unroll
        for (int p = 0; p < NP; p++) acc[r4][p] = 0ull;

    const int kbase = q * KQ;
    const int tid64 = lane + h * 32;

    for (int kt = 0; kt < KQ / 16; kt++) {
        const int k0 = kbase + kt * 16;
        // stage 128 rows x 16 k for this quarter.
        // Lane map: c4 = idx&3, rr = idx>>2 -> 4 lanes cover one row's 64B slice
        // (8 L1 lines per inst instead of 32).
#pragma unroll
        for (int it = 0; it < 8; it++) {
            int idx = tid64 + it * 64;
            int rr = idx >> 2, c4 = idx & 3;
            float4 v = __ldcg(reinterpret_cast<const float4*>(x1 + src[rr] + k0) + c4);
            u->Xs[q][c4 * 4 + 0][rr] = v.x;
            u->Xs[q][c4 * 4 + 1][rr] = v.y;
            u->Xs[q][c4 * 4 + 2][rr] = v.z;
            u->Xs[q][c4 * 4 + 3][rr] = v.w;
        }
        __syncthreads();

#pragma unroll
        for (int kk = 0; kk < 16; kk++) {
            unsigned long long px[4];
#pragma unroll
            for (int r4 = 0; r4 < 4; r4++) {
                float x = u->Xs[q][kk][lane + 32 * r4];
                px[r4] = pack2(x, x);
            }
            const ulonglong2* wrow =
                reinterpret_cast<const ulonglong2*>(W + (k0 + kk) * 36 + coloff);
#pragma unroll
            for (int p = 0; p < NP / 2; p++) {
                ulonglong2 w = __ldg(wrow + p);     // uniform LDG.128, L1-hit
#pragma unroll
                for (int r4 = 0; r4 < 4; r4++) {
                    acc[r4][2 * p]     = fma2(px[r4], w.x, acc[r4][2 * p]);
                    acc[r4][2 * p + 1] = fma2(px[r4], w.y, acc[r4][2 * p + 1]);
                }
            }
        }
        __syncthreads();
    }

    if (q != 0) {
#pragma unroll
        for (int r4 = 0; r4 < 4; r4++) {
            const int row = lane + 32 * r4;
#pragma unroll
            for (int p = 0; p < NP; p++) {
                float a, b; unpack2(acc[r4][p], a, b);
                u->part[q - 1][row][coloff + 2 * p]     = a;
                u->part[q - 1][row][coloff + 2 * p + 1] = b;
            }
        }
    }
    __syncthreads();
    if (q == 0) {
#pragma unroll
        for (int r4 = 0; r4 < 4; r4++) {
            const int row = lane + 32 * r4;
            const long long grow = rowbase + row;
            float ev[2 * NP], eev[2 * NP];
#pragma unroll
            for (int p = 0; p < NP; p++) {
                float a, b; unpack2(acc[r4][p], a, b);
                int c0 = coloff + 2 * p;
                float v0 = a + u->part[0][row][c0] + u->part[1][row][c0] +
                           u->part[2][row][c0] + bias[c0];
                float v1 = b + u->part[0][row][c0 + 1] + u->part[1][row][c0 + 1] +
                           u->part[2][row][c0 + 1] + bias[c0 + 1];
                v0 = (v0 >= 0.f) ? v0 : 0.01f * v0;
                v1 = (v1 >= 0.f) ? v1 : 0.01f * v1;
                ev[2 * p] = v0;  ev[2 * p + 1] = v1;
                eev[2 * p] = __expf(v0);  eev[2 * p + 1] = __expf(v1);
            }
            float4* pe  = reinterpret_cast<float4*>(g_emit  + grow * 36 + coloff);
            float4* pee = reinterpret_cast<float4*>(g_eemit + grow * 36 + coloff);
#pragma unroll
            for (int c4 = 0; c4 < NP / 2; c4++) {
                pe[c4]  = make_float4(ev[4*c4],  ev[4*c4+1],  ev[4*c4+2],  ev[4*c4+3]);
                pee[c4] = make_float4(eev[4*c4], eev[4*c4+1], eev[4*c4+2], eev[4*c4+3]);
            }
        }
    }
}

// ---------------- fused kernel ----------------
// blocks [0,64):    combined scan for batch bid: NLL = thr 0-63 (bar 1),
//                   Viterbi = thr 64-127 (bar 2); thr 128+ exit
// blocks [64,320):  GEMM, chunk-major: c=(bid-64)>>6, b=(bid-64)&63, 128 rows
// block  320:       loss reducer
__global__ __launch_bounds__(256, 2) void fused_kernel(
    const float* __restrict__ x1, const int* __restrict__ hidx,
    const float* __restrict__ W, const float* __restrict__ bias,
    const int* __restrict__ tags, const float* __restrict__ trans,
    float* __restrict__ out)
{
    __shared__ __align__(16) SmemU u;
    __shared__ int   src[128];
    __shared__ __align__(16) float bufN[2][NT];
    __shared__ __align__(16) float bufV[2][NT];
    __shared__ float redN[64], redV[64];
    __shared__ int   iredN[64], iredV[64];
    __shared__ int   sh_xlenN, sh_xlenV, sh_lastV;

    const int tid = threadIdx.x;
    const int bid = blockIdx.x;

    if (bid >= SCAN_BLOCKS && bid < SCAN_BLOCKS + GEMM_BLOCKS) {
        // ================= GEMM =================
        const int gb = bid - SCAN_BLOCKS;
        const int c  = gb >> 6;          // chunk 0..3
        const int b  = gb & 63;          // batch
        const int rowbase = b * SS + c * CHUNK;
        const int warp = tid >> 5;
        const int q = warp >> 1;
        const int h = warp & 1;
        const int lane = tid & 31;

        if (tid < 128) {
            int g = rowbase + tid;
            src[tid] = (b << 9) * HH + hidx[g] * HH;
        }
        __syncthreads();

        if (h == 0) gemm_half<8 >(&u, x1, W, bias, src, q, 0, lane, rowbase);
        else        gemm_half<10>(&u, x1, W, bias, src, q, 1, lane, rowbase);

        __syncthreads();
        if (tid == 0) {
            __threadfence();
            atomicExch(&g_done[b * 4 + c], 1);
        }
        return;
    }

    if (bid >= SCAN_BLOCKS + GEMM_BLOCKS) {
        // ================= loss reducer =================
        if (tid == 0) {
            volatile int* c = &g_nllcnt;
            while (*c < BB) __nanosleep(256);
            __threadfence();
            float a = 0.f;
            for (int i = 0; i < BB; i++) a += g_lossb[i];
            out[0] = a;
        }
        return;
    }

    // ================= SCANS =================
    const int b = bid;

    if (tid < 64) {
        // ---------------- NLL (threads 0-63, named barrier 1) ----------------
        const int j = tid;
        {
            int lm = 0;
            for (int s = tid; s < SS; s += 64) lm = max(lm, hidx[b * SS + s]);
            iredN[tid] = lm;
            nbar(1);
            if (tid == 0) {
                int m = 0;
                for (int i = 0; i < 64; i++) m = max(m, iredN[i]);
                sh_xlenN = m;
            }
            nbar(1);
        }
        const int xlen = sh_xlenN;
        const int cmax = (xlen - 1) >> 7;
        int sready = 0;

        float* Tsh = u.s.Tsh;
        for (int i = tid; i < NT * NT; i += 64) Tsh[i] = trans[i];
        nbar(1);

        unsigned long long Ecol2[18];
        float Cl = 0.f;
        if (j < NT) {
#pragma unroll
            for (int p = 0; p < 18; p++)
                Ecol2[p] = pack2(__expf(Tsh[(2 * p) * NT + j]),
                                 __expf(Tsh[(2 * p + 1) * NT + j]));
        }

        if (tid == 0) { wait_flag(b * 4 + 0); sready = 1; __threadfence(); }
        nbar(1);

        if (j < NT)
            bufN[0][j] = __expf(g_emit[(b * SS) * NT + j] + Tsh[TSTART * NT + j]);
        nbar(1);

        const float* ee = g_eemit + (long long)b * SS * NT;
        float eenext = (xlen > 1 && j < NT) ? ee[NT + j] : 0.f;
        int t = 1;
        for (int c = 0; c <= cmax; c++) {
            const int wc = min(c + 1, cmax);
            if (tid == 0) {
                for (; sready <= wc; sready++) wait_flag(b * 4 + sready);
                __threadfence();
            }
            nbar(1);
            const int tend = min((c + 1) * CHUNK, xlen);
            for (; t < tend; t++) {
                const int cur = t & 1, prev = cur ^ 1;
                float eecur = eenext;
                if (t + 1 < xlen && j < NT) eenext = ee[(t + 1) * NT + j];
                if (j < NT) {
                    const unsigned long long* vp =
                        reinterpret_cast<const unsigned long long*>(&bufN[prev][0]);
                    unsigned long long c0 = 0, c1 = 0, c2 = 0, c3 = 0;
                    float m0 = 0.f, m1 = 0.f, m2 = 0.f, m3 = 0.f;
#pragma unroll
                    for (int p = 0; p < 16; p += 4) {
                        unsigned long long v0 = vp[p], v1 = vp[p+1], v2 = vp[p+2], v3 = vp[p+3];
                        c0 = fma2(v0, Ecol2[p],   c0);
                        c1 = fma2(v1, Ecol2[p+1], c1);
                        c2 = fma2(v2, Ecol2[p+2], c2);
                        c3 = fma2(v3, Ecol2[p+3], c3);
                        float a, bb2;
                        unpack2(v0, a, bb2); m0 = fmaxf(m0, fmaxf(a, bb2));
                        unpack2(v1, a, bb2); m1 = fmaxf(m1, fmaxf(a, bb2));
                        unpack2(v2, a, bb2); m2 = fmaxf(m2, fmaxf(a, bb2));
                        unpack2(v3, a, bb2); m3 = fmaxf(m3, fmaxf(a, bb2));
                    }
                    {
                        unsigned long long v0 = vp[16], v1 = vp[17];
                        c0 = fma2(v0, Ecol2[16], c0);
                        c1 = fma2(v1, Ecol2[17], c1);
                        float a, bb2;
                        unpack2(v0, a, bb2); m0 = fmaxf(m0, fmaxf(a, bb2));
                        unpack2(v1, a, bb2); m1 = fmaxf(m1, fmaxf(a, bb2));
                    }
                    unsigned long long cs = add2(add2(c0, c1), add2(c2, c3));
                    float sa, sbv; unpack2(cs, sa, sbv);
                    float accv = sa + sbv;
                    float m = fmaxf(fmaxf(m0, m1), fmaxf(m2, m3));
                    bufN[cur][j] = accv * (1.0f / m) * eecur;
                    Cl += __logf(m);
                }
                nbar(1);
            }
        }
        const int lastbuf = (xlen >= 2) ? ((xlen - 1) & 1) : 0;
        if (j < NT) redN[j] = bufN[lastbuf][j] * __expf(Tsh[j * NT + TSTOP]);
        nbar(1);

        float logZ = 0.f;
        if (tid == 0) {
            float sZ = 0.f;
            for (int i = 0; i < NT; i++) sZ += redN[i];
            logZ = Cl + __logf(sZ);
        }
        nbar(1);

        const int* tg = tags + b * SS;
        {
            float gp = 0.f;
            for (int s = tid; s < xlen; s += 64) {
                int cs = tg[s];
                gp += g_emit[((long long)b * SS + s) * NT + cs];
                if (s >= 1) gp += Tsh[tg[s - 1] * NT + cs];
            }
            redN[tid] = gp;
        }
        nbar(1);
        if (tid == 0) {
            float g = 0.f;
            for (int i = 0; i < 64; i++) g += redN[i];
            int li = (xlen > 0) ? (xlen - 1) : 0;
            g += Tsh[TSTART * NT + tg[0]] + Tsh[tg[li] * NT + TSTOP];
            g_lossb[b] = logZ - g;
            __threadfence();
            atomicAdd(&g_nllcnt, 1);
        }
        return;
    }

    if (tid < 128) {
        // ---------------- Viterbi (threads 64-127, named barrier 2) ----------------
        const int lt = tid - 64;
        const int j = lt;
        {
            int lm = 0;
            for (int s = lt; s < SS; s += 64) lm = max(lm, hidx[b * SS + s]);
            iredV[lt] = lm;
            nbar(2);
            if (lt == 0) {
                int m = 0;
                for (int i = 0; i < 64; i++) m = max(m, iredV[i]);
                sh_xlenV = m;
            }
            nbar(2);
        }
        const int xlen = sh_xlenV;
        const int cmax = (xlen - 1) >> 7;
        int sready = 0;

        unsigned char* bp = u.s.bp;
        float Tcol[NT];
        float TjS = 0.f;
        if (j < NT) {
#pragma unroll
            for (int i = 0; i < NT; i++) Tcol[i] = trans[i * NT + j];
            TjS = trans[j * NT + TSTOP];
        }

        if (lt == 0) { wait_flag(b * 4 + 0); sready = 1; __threadfence(); }
        nbar(2);

        if (j < NT)
            bufV[0][j] = g_emit[(b * SS) * NT + j] + trans[TSTART * NT + j];
        nbar(2);

        const float* em = g_emit + (long long)b * SS * NT;
        float emnext = (xlen > 1 && j < NT) ? em[NT + j] : 0.f;
        int t = 1;
        for (int c = 0; c <= cmax; c++) {
            const int wc = min(c + 1, cmax);
            if (lt == 0) {
                for (; sready <= wc; sready++) wait_flag(b * 4 + sready);
                __threadfence();
            }
            nbar(2);
            const int tend = min((c + 1) * CHUNK, xlen);
            for (; t < tend; t++) {
                const int cur = t & 1, prev = cur ^ 1;
                float ec = emnext;
                if (t + 1 < xlen && j < NT) emnext = em[(t + 1) * NT + j];
                if (j < NT) {
                    float bb4[4] = {-1e30f, -1e30f, -1e30f, -1e30f};
                    int   bi4[4] = {0, 9, 18, 27};
#pragma unroll
                    for (int c4 = 0; c4 < 4; c4++) {
#pragma unroll
                        for (int k = 0; k < 9; k++) {
                            int i = c4 * 9 + k;
                            float v = bufV[prev][i] + Tcol[i];
                            bool gt = v > bb4[c4];
                            bb4[c4] = gt ? v : bb4[c4];
                            bi4[c4] = gt ? i : bi4[c4];
                        }
                    }
                    float best = bb4[0]; int bi = bi4[0];
                    if (bb4[1] > best) { best = bb4[1]; bi = bi4[1]; }
                    if (bb4[2] > best) { best = bb4[2]; bi = bi4[2]; }
                    if (bb4[3] > best) { best = bb4[3]; bi = bi4[3]; }
                    bufV[cur][j] = best + ec;
                    bp[(t - 1) * NT + j] = (unsigned char)bi;
                }
                nbar(2);
            }
        }
        const int lastbuf = (xlen >= 2) ? ((xlen - 1) & 1) : 0;
        if (j < NT) redV[j] = bufV[lastbuf][j] + TjS;
        nbar(2);
        if (lt == 0) {
            float bs = -1e30f; int ltag = 0;
            for (int i = 0; i < NT; i++) {
                float v = redV[i];
                if (v > bs) { bs = v; ltag = i; }
            }
            out[1 + BB * SS + b] = bs;
            sh_lastV = ltag;
        }
        nbar(2);

        float* op = out + 1 + b * SS;
        for (int s = xlen + lt; s < SS; s += 64) op[s] = 0.f;
        if (lt == 0 && xlen > 0) {
            int tag = sh_lastV;
            op[xlen - 1] = (float)tag;
            for (int t2 = xlen - 1; t2 >= 1; t2--) {
                tag = bp[(t2 - 1) * NT + tag];
                op[t2 - 1] = (float)tag;
            }
        }
        return;
    }
    // threads 128-255 of scan blocks: exit
}

extern "C" void kernel_launch(void* const* d_in, const int* in_sizes, int n_in,
                              void* d_out, int out_size) {
    const float* x1    = (const float*)d_in[0];
    const int*   hidx  = (const int*)  d_in[1];
    const int*   tags  = (const int*)  d_in[2];
    const float* W     = (const float*)d_in[3];
    const float* bias  = (const float*)d_in[4];
    const float* trans = (const float*)d_in[5];
    float* out = (float*)d_out;

    init_kernel<<<1, 256>>>();
    fused_kernel<<<SCAN_BLOCKS + GEMM_BLOCKS + 1, 256>>>(
        x1, hidx, W, bias, tags, trans, out);
}